// round 1
// baseline (speedup 1.0000x reference)
#include <cuda_runtime.h>
#include <math.h>

// Problem constants (from reference setup_inputs)
#define B 8
#define C 64
#define SPATIAL (48*48*48)        // 110592 floats per (b,c) channel
#define SPATIAL4 (SPATIAL/4)      // 27648 float4 per channel
#define R 8
#define NEG_SLOPE 0.01f

// Scratch (no cudaMalloc allowed)
__device__ float g_means[B * C];
__device__ int   g_idx[B * R];

// ---------------------------------------------------------------------------
// Kernel 1: per-(b,c) spatial mean. One block per row, vectorized loads,
// double accumulation so the downstream top-k selection is bit-stable.
// ---------------------------------------------------------------------------
__global__ __launch_bounds__(256) void mean_kernel(const float* __restrict__ x,
                                                   float* __restrict__ means) {
    const int row = blockIdx.x;  // b*C + c, 0..511
    const float4* __restrict__ p =
        reinterpret_cast<const float4*>(x + (size_t)row * SPATIAL);

    double acc = 0.0;
    for (int i = threadIdx.x; i < SPATIAL4; i += 256) {
        float4 v = p[i];
        acc += (double)v.x + (double)v.y + (double)v.z + (double)v.w;
    }

    // warp reduce
    for (int off = 16; off > 0; off >>= 1)
        acc += __shfl_down_sync(0xFFFFFFFFu, acc, off);

    __shared__ double warp_sums[8];
    const int lane = threadIdx.x & 31;
    const int wid  = threadIdx.x >> 5;
    if (lane == 0) warp_sums[wid] = acc;
    __syncthreads();

    if (wid == 0) {
        double s = (lane < 8) ? warp_sums[lane] : 0.0;
        for (int off = 4; off > 0; off >>= 1)
            s += __shfl_down_sync(0xFFFFFFFFu, s, off);
        if (lane == 0)
            means[row] = (float)(s / (double)SPATIAL);
    }
}

// ---------------------------------------------------------------------------
// Kernel 2: tiny MLP (64->64 leaky relu, 64->64 sigmoid) + top-8 per batch.
// One block, 512 threads: thread t handles (b = t/64, i = t%64).
// ---------------------------------------------------------------------------
__global__ __launch_bounds__(512) void mlp_topk_kernel(
    const float* __restrict__ means,
    const float* __restrict__ w1, const float* __restrict__ b1,
    const float* __restrict__ w2, const float* __restrict__ b2,
    int* __restrict__ idx_out) {
    __shared__ float sm[B * C];
    __shared__ float y1[B * C];
    __shared__ float y2[B * C];

    const int t = threadIdx.x;       // 0..511
    sm[t] = means[t];
    __syncthreads();

    const int b = t >> 6;
    const int i = t & 63;

    // y1[b][i] = leaky( sum_j means[b][j] * w1[i][j] + b1[i] )
    float acc = b1[i];
    const float* __restrict__ w1row = w1 + i * C;
    const float* __restrict__ mrow  = sm + b * C;
#pragma unroll 16
    for (int j = 0; j < C; j++) acc += mrow[j] * w1row[j];
    y1[t] = (acc > 0.0f) ? acc : NEG_SLOPE * acc;
    __syncthreads();

    // y2[b][i] = sigmoid( sum_j y1[b][j] * w2[i][j] + b2[i] )
    acc = b2[i];
    const float* __restrict__ w2row = w2 + i * C;
    const float* __restrict__ y1row = y1 + b * C;
#pragma unroll 16
    for (int j = 0; j < C; j++) acc += y1row[j] * w2row[j];
    y2[t] = 1.0f / (1.0f + expf(-acc));
    __syncthreads();

    // top-8 selection per batch (thread b < 8). Strict '>' keeps the earliest
    // index on ties, matching jax.lax.top_k.
    if (t < B) {
        float v[C];
#pragma unroll
        for (int j = 0; j < C; j++) v[j] = y2[t * C + j];
#pragma unroll
        for (int r = 0; r < R; r++) {
            int   best_j = 0;
            float best_v = v[0];
#pragma unroll
            for (int j = 1; j < C; j++) {
                if (v[j] > best_v) { best_v = v[j]; best_j = j; }
            }
            idx_out[t * R + r] = best_j;
            v[best_j] = -1.0f;   // sigmoid outputs are in (0,1)
        }
    }
}

// ---------------------------------------------------------------------------
// Kernel 3: gather the selected channels: out[b][r][:] = x[b][idx[b][r]][:]
// grid = (SPATIAL4/256, B*R), float4 copies.
// ---------------------------------------------------------------------------
__global__ __launch_bounds__(256) void gather_kernel(const float* __restrict__ x,
                                                     const int* __restrict__ idx,
                                                     float* __restrict__ out) {
    const int row = blockIdx.y;          // 0..63 : b*R + r
    const int b   = row >> 3;
    const int ch  = idx[row];

    const float4* __restrict__ src =
        reinterpret_cast<const float4*>(x + ((size_t)b * C + ch) * SPATIAL);
    float4* __restrict__ dst =
        reinterpret_cast<float4*>(out + (size_t)row * SPATIAL);

    const int i = blockIdx.x * 256 + threadIdx.x;
    if (i < SPATIAL4) dst[i] = src[i];
}

// ---------------------------------------------------------------------------
extern "C" void kernel_launch(void* const* d_in, const int* in_sizes, int n_in,
                              void* d_out, int out_size) {
    const float* x  = (const float*)d_in[0];
    const float* w1 = (const float*)d_in[1];
    const float* b1 = (const float*)d_in[2];
    const float* w2 = (const float*)d_in[3];
    const float* b2 = (const float*)d_in[4];
    float* out = (float*)d_out;

    float* means;
    int* idx;
    cudaGetSymbolAddress((void**)&means, g_means);
    cudaGetSymbolAddress((void**)&idx, g_idx);

    mean_kernel<<<B * C, 256>>>(x, means);
    mlp_topk_kernel<<<1, 512>>>(means, w1, b1, w2, b2, idx);
    dim3 grid((SPATIAL4 + 255) / 256, B * R);
    gather_kernel<<<grid, 256>>>(x, idx, out);
}

// round 2
// speedup vs baseline: 3.4413x; 3.4413x over previous
#include <cuda_runtime.h>
#include <math.h>

// Problem constants (from reference setup_inputs)
#define B 8
#define C 64
#define SPATIAL (48*48*48)        // 110592 floats per (b,c) channel
#define SPATIAL4 (SPATIAL/4)      // 27648 float4 per channel
#define R 8
#define NEG_SLOPE 0.01f

// Scratch (no cudaMalloc allowed)
__device__ float g_means[B * C];
__device__ int   g_idx[B * R];

// ---------------------------------------------------------------------------
// Kernel 1: per-(b,c) spatial mean. One block per row, float4 loads,
// 4 independent float accumulators (no dependent FP64 chain).
// 27648 float4 per row / 256 threads = 108 iterations per thread.
// ---------------------------------------------------------------------------
__global__ __launch_bounds__(256) void mean_kernel(const float* __restrict__ x,
                                                   float* __restrict__ means) {
    const int row = blockIdx.x;  // b*C + c, 0..511
    const float4* __restrict__ p =
        reinterpret_cast<const float4*>(x + (size_t)row * SPATIAL);

    float ax = 0.f, ay = 0.f, az = 0.f, aw = 0.f;
#pragma unroll 4
    for (int i = threadIdx.x; i < SPATIAL4; i += 256) {
        float4 v = p[i];
        ax += v.x; ay += v.y; az += v.z; aw += v.w;
    }
    float acc = (ax + ay) + (az + aw);

    // warp reduce
    for (int off = 16; off > 0; off >>= 1)
        acc += __shfl_down_sync(0xFFFFFFFFu, acc, off);

    __shared__ float warp_sums[8];
    const int lane = threadIdx.x & 31;
    const int wid  = threadIdx.x >> 5;
    if (lane == 0) warp_sums[wid] = acc;
    __syncthreads();

    if (wid == 0) {
        float s = (lane < 8) ? warp_sums[lane] : 0.f;
        for (int off = 4; off > 0; off >>= 1)
            s += __shfl_down_sync(0xFFFFFFFFu, s, off);
        if (lane == 0)
            means[row] = s * (1.0f / (float)SPATIAL);
    }
}

// ---------------------------------------------------------------------------
// Kernel 2: tiny MLP (64->64 leaky relu, 64->64 sigmoid) + top-8 per batch.
// One block, 512 threads: thread t handles (b = t/64, i = t%64).
// ---------------------------------------------------------------------------
__global__ __launch_bounds__(512) void mlp_topk_kernel(
    const float* __restrict__ means,
    const float* __restrict__ w1, const float* __restrict__ b1,
    const float* __restrict__ w2, const float* __restrict__ b2,
    int* __restrict__ idx_out) {
    __shared__ float sm[B * C];
    __shared__ float y1[B * C];
    __shared__ float y2[B * C];

    const int t = threadIdx.x;       // 0..511
    sm[t] = means[t];
    __syncthreads();

    const int b = t >> 6;
    const int i = t & 63;

    // y1[b][i] = leaky( sum_j means[b][j] * w1[i][j] + b1[i] )
    float acc = b1[i];
    const float* __restrict__ w1row = w1 + i * C;
    const float* __restrict__ mrow  = sm + b * C;
#pragma unroll 16
    for (int j = 0; j < C; j++) acc += mrow[j] * w1row[j];
    y1[t] = (acc > 0.0f) ? acc : NEG_SLOPE * acc;
    __syncthreads();

    // y2[b][i] = sigmoid( sum_j y1[b][j] * w2[i][j] + b2[i] )
    acc = b2[i];
    const float* __restrict__ w2row = w2 + i * C;
    const float* __restrict__ y1row = y1 + b * C;
#pragma unroll 16
    for (int j = 0; j < C; j++) acc += y1row[j] * w2row[j];
    y2[t] = 1.0f / (1.0f + expf(-acc));
    __syncthreads();

    // top-8 selection per batch (thread b < 8). Strict '>' keeps the earliest
    // index on ties, matching jax.lax.top_k.
    if (t < B) {
        float v[C];
#pragma unroll
        for (int j = 0; j < C; j++) v[j] = y2[t * C + j];
#pragma unroll
        for (int r = 0; r < R; r++) {
            int   best_j = 0;
            float best_v = v[0];
#pragma unroll
            for (int j = 1; j < C; j++) {
                if (v[j] > best_v) { best_v = v[j]; best_j = j; }
            }
            idx_out[t * R + r] = best_j;
            v[best_j] = -1.0f;   // sigmoid outputs are in (0,1)
        }
    }
}

// ---------------------------------------------------------------------------
// Kernel 3: gather selected channels: out[b][r][:] = x[b][idx[b][r]][:]
// grid = (27, 64); each thread copies 4 float4 (strided) for MLP.
// 27648 float4 per row = 27 blocks * 256 threads * 4.
// ---------------------------------------------------------------------------
__global__ __launch_bounds__(256) void gather_kernel(const float* __restrict__ x,
                                                     const int* __restrict__ idx,
                                                     float* __restrict__ out) {
    const int row = blockIdx.y;          // 0..63 : b*R + r
    const int b   = row >> 3;
    const int ch  = idx[row];

    const float4* __restrict__ src =
        reinterpret_cast<const float4*>(x + ((size_t)b * C + ch) * SPATIAL);
    float4* __restrict__ dst =
        reinterpret_cast<float4*>(out + (size_t)row * SPATIAL);

    const int base = blockIdx.x * (256 * 4) + threadIdx.x;
#pragma unroll
    for (int k = 0; k < 4; k++) {
        const int i = base + k * 256;
        dst[i] = src[i];   // SPATIAL4 = 27648 exactly divisible: no bounds check
    }
}

// ---------------------------------------------------------------------------
extern "C" void kernel_launch(void* const* d_in, const int* in_sizes, int n_in,
                              void* d_out, int out_size) {
    const float* x  = (const float*)d_in[0];
    const float* w1 = (const float*)d_in[1];
    const float* b1 = (const float*)d_in[2];
    const float* w2 = (const float*)d_in[3];
    const float* b2 = (const float*)d_in[4];
    float* out = (float*)d_out;

    float* means;
    int* idx;
    cudaGetSymbolAddress((void**)&means, g_means);
    cudaGetSymbolAddress((void**)&idx, g_idx);

    mean_kernel<<<B * C, 256>>>(x, means);
    mlp_topk_kernel<<<1, 512>>>(means, w1, b1, w2, b2, idx);
    dim3 grid(SPATIAL4 / (256 * 4), B * R);   // (27, 64)
    gather_kernel<<<grid, 256>>>(x, idx, out);
}